// round 10
// baseline (speedup 1.0000x reference)
#include <cuda_runtime.h>
#include <cuda_fp16.h>
#include <cstdint>

// Problem constants: N=8, T=200, U=100, D=512, V=500
#define JN 8
#define JT 200
#define JU 100
#define JD 512
#define JV 500
#define JM (JN * JT * JU)   // 160000

// Fused kernel: CTA 128(M) x 128(N), BK=64 fp16 (128B rows, SW128), 2-stage ring
#define TM 128
#define TN 128
#define BKT 64
#define NTILE (JD / BKT)          // 8
#define ASZ (TM * BKT * 2)        // 16384 B
#define BSZ (TN * BKT * 2)        // 16384 B
#define STAGE (ASZ + BSZ)         // 32768 B
#define DSMEM (2 * STAGE)         // 65536 B

// ---------------------------------------------------------------------------
__device__ __forceinline__ float fast_tanh(float x) {
    float e = __expf(2.0f * x);
    return 1.0f - __fdividef(2.0f, e + 1.0f);
}

// ============================ Fused kernel =================================
// out[M,V] = tanh(enc+dec)[M,K](fp16) @ W[V,K](fp16)^T + bias
// Threads 0-127: produce A rows (LDG fp32 -> tanh -> fp16 -> STS).
// Threads 128-255: produce B rows (LDG W fp32 -> fp16 -> STS, zero-pad >=500).
// 8 warps compute: 2(M) x 4(N), warp 64x32, mma.m16n8k16.f16 fp32-acc.
__global__ __launch_bounds__(256, 2)
void joiner_fused(const float* __restrict__ enc, const float* __restrict__ dec,
                  const float* __restrict__ W,   const float* __restrict__ bias,
                  float* __restrict__ out)
{
    extern __shared__ char dsm[];
    const uint32_t smem0 = (uint32_t)__cvta_generic_to_shared(dsm);

    const int tid  = threadIdx.x;
    const int lane = tid & 31;
    const int wid  = tid >> 5;
    const int g    = lane >> 2;     // 0..7
    const int tg   = lane & 3;      // 0..3
    const int wm   = wid & 1;       // warp M row (64 each)
    const int wn   = wid >> 1;      // warp N col (32 each)

    const int m0 = blockIdx.y * TM;
    const int v0 = blockIdx.x * TN;

    // ---- producer roles ----------------------------------------------------
    const bool isA  = tid < 128;
    const int  prow = isA ? tid : (tid - 128);     // row within tile
    const float* ep = nullptr;
    const float* dp = nullptr;
    const float* wp = nullptr;
    bool wvalid = false;
    if (isA) {
        const int m = m0 + prow;
        const int n = m / (JT * JU);
        const int r2 = m % (JT * JU);
        const int t = r2 / JU;
        const int u = r2 % JU;
        ep = enc + (size_t)(n * JT + t) * JD;
        dp = dec + (size_t)(n * JU + u) * JD;
    } else {
        const int wr = v0 + prow;
        wvalid = (wr < JV);
        wp = W + (size_t)(wvalid ? wr : 0) * JD;
    }
    const uint32_t pBase = (uint32_t)((isA ? 0 : ASZ) + prow * 128);
    const int pXor = prow & 7;

    // produce tile `it` (k range [it*64, it*64+64)) into buffer it&1
    auto produce = [&](int it) {
        const uint32_t base = smem0 + (uint32_t)((it & 1) * STAGE) + pBase;
        const int ko = it * BKT;
        if (isA) {
            #pragma unroll
            for (int s = 0; s < 8; s++) {            // 8 k-values per seg
                const float4 e0 = *(const float4*)(ep + ko + 8 * s);
                const float4 e1 = *(const float4*)(ep + ko + 8 * s + 4);
                const float4 d0 = *(const float4*)(dp + ko + 8 * s);
                const float4 d1 = *(const float4*)(dp + ko + 8 * s + 4);
                __half2 h[4];
                h[0] = __floats2half2_rn(fast_tanh(e0.x + d0.x), fast_tanh(e0.y + d0.y));
                h[1] = __floats2half2_rn(fast_tanh(e0.z + d0.z), fast_tanh(e0.w + d0.w));
                h[2] = __floats2half2_rn(fast_tanh(e1.x + d1.x), fast_tanh(e1.y + d1.y));
                h[3] = __floats2half2_rn(fast_tanh(e1.z + d1.z), fast_tanh(e1.w + d1.w));
                const uint4 v = *(const uint4*)h;
                asm volatile("st.shared.v4.b32 [%0], {%1,%2,%3,%4};"
                             :: "r"(base + 16u * (uint32_t)(s ^ pXor)),
                                "r"(v.x), "r"(v.y), "r"(v.z), "r"(v.w) : "memory");
            }
        } else {
            #pragma unroll
            for (int s = 0; s < 8; s++) {
                __half2 h[4] = {__half2{}, __half2{}, __half2{}, __half2{}};
                if (wvalid) {
                    const float4 w0 = *(const float4*)(wp + ko + 8 * s);
                    const float4 w1 = *(const float4*)(wp + ko + 8 * s + 4);
                    h[0] = __floats2half2_rn(w0.x, w0.y);
                    h[1] = __floats2half2_rn(w0.z, w0.w);
                    h[2] = __floats2half2_rn(w1.x, w1.y);
                    h[3] = __floats2half2_rn(w1.z, w1.w);
                }
                const uint4 v = *(const uint4*)h;
                asm volatile("st.shared.v4.b32 [%0], {%1,%2,%3,%4};"
                             :: "r"(base + 16u * (uint32_t)(s ^ pXor)),
                                "r"(v.x), "r"(v.y), "r"(v.z), "r"(v.w) : "memory");
            }
        }
    };

    // ---- ldmatrix per-lane geometry (identical to proven R9 mapping) -------
    const int lr = (lane & 7) + 8 * ((lane >> 3) & 1);  // row within 16-row frag
    const int kh = lane >> 4;                           // k-half (0/1)
    uint32_t aOff[4], bOff[2];
    int aXk[4], bXk[2];
    #pragma unroll
    for (int mt = 0; mt < 4; mt++) {
        const int row = wm * 64 + mt * 16 + lr;
        aOff[mt] = (uint32_t)(row * 128);
        aXk[mt]  = row & 7;
    }
    #pragma unroll
    for (int pr = 0; pr < 2; pr++) {
        const int row = wn * 32 + pr * 16 + lr;
        bOff[pr] = (uint32_t)(ASZ + row * 128);
        bXk[pr]  = row & 7;
    }

    float acc[4][4][4];
    #pragma unroll
    for (int mt = 0; mt < 4; mt++)
        #pragma unroll
        for (int nt = 0; nt < 4; nt++)
            #pragma unroll
            for (int i = 0; i < 4; i++) acc[mt][nt][i] = 0.0f;

    // ---- pipeline: produce(it+1) overlaps compute(it); occ=2 hides bubbles -
    produce(0);

    #pragma unroll 1
    for (int it = 0; it < NTILE; ++it) {
        __syncthreads();                 // tile `it` visible; all warps past it-1
        if (it + 1 < NTILE) produce(it + 1);

        const uint32_t sb = smem0 + (uint32_t)((it & 1) * STAGE);

        #pragma unroll
        for (int ks = 0; ks < BKT / 16; ks++) {  // 4 k16 slices
            unsigned a[4][4], b[4][2];
            const int ksk = (ks << 1) | kh;
            #pragma unroll
            for (int mt = 0; mt < 4; mt++) {
                const uint32_t ad = sb + aOff[mt] + 16u * (uint32_t)(ksk ^ aXk[mt]);
                asm volatile("ldmatrix.sync.aligned.m8n8.x4.shared.b16 {%0,%1,%2,%3}, [%4];"
                             : "=r"(a[mt][0]), "=r"(a[mt][1]), "=r"(a[mt][2]), "=r"(a[mt][3])
                             : "r"(ad));
            }
            #pragma unroll
            for (int pr = 0; pr < 2; pr++) {
                const uint32_t bd = sb + bOff[pr] + 16u * (uint32_t)(ksk ^ bXk[pr]);
                unsigned r0, r1, r2, r3;
                asm volatile("ldmatrix.sync.aligned.m8n8.x4.shared.b16 {%0,%1,%2,%3}, [%4];"
                             : "=r"(r0), "=r"(r1), "=r"(r2), "=r"(r3) : "r"(bd));
                b[pr * 2 + 0][0] = r0;  b[pr * 2 + 1][0] = r1;
                b[pr * 2 + 0][1] = r2;  b[pr * 2 + 1][1] = r3;
            }
            #pragma unroll
            for (int mt = 0; mt < 4; mt++)
                #pragma unroll
                for (int nt = 0; nt < 4; nt++) {
                    asm volatile(
                        "mma.sync.aligned.m16n8k16.row.col.f32.f16.f16.f32 "
                        "{%0,%1,%2,%3}, {%4,%5,%6,%7}, {%8,%9}, {%0,%1,%2,%3};"
                        : "+f"(acc[mt][nt][0]), "+f"(acc[mt][nt][1]),
                          "+f"(acc[mt][nt][2]), "+f"(acc[mt][nt][3])
                        : "r"(a[mt][0]), "r"(a[mt][1]), "r"(a[mt][2]), "r"(a[mt][3]),
                          "r"(b[nt][0]), "r"(b[nt][1]));
                }
        }
    }

    // ---- epilogue: bias + float2 stores ------------------------------------
    #pragma unroll
    for (int mt = 0; mt < 4; mt++) {
        const int r0 = m0 + wm * 64 + mt * 16 + g;
        const int r1 = r0 + 8;
        #pragma unroll
        for (int nt = 0; nt < 4; nt++) {
            const int c = v0 + wn * 32 + nt * 8 + tg * 2;
            if (c < JV) {
                const float2 bb2 = *(const float2*)(bias + c);
                float2 o0, o1;
                o0.x = acc[mt][nt][0] + bb2.x;
                o0.y = acc[mt][nt][1] + bb2.y;
                o1.x = acc[mt][nt][2] + bb2.x;
                o1.y = acc[mt][nt][3] + bb2.y;
                *(float2*)(out + (size_t)r0 * JV + c) = o0;
                *(float2*)(out + (size_t)r1 * JV + c) = o1;
            }
        }
    }
}

// ===========================================================================
extern "C" void kernel_launch(void* const* d_in, const int* in_sizes, int n_in,
                              void* d_out, int out_size)
{
    const float* enc  = (const float*)d_in[0];  // (8, 200, 512)
    const float* dec  = (const float*)d_in[1];  // (8, 100, 512)
    const float* W    = (const float*)d_in[2];  // (500, 512)
    const float* bias = (const float*)d_in[3];  // (500,)
    float* out = (float*)d_out;                 // (8, 200, 100, 500)

    cudaFuncSetAttribute(joiner_fused, cudaFuncAttributeMaxDynamicSharedMemorySize, DSMEM);
    dim3 grid(4, JM / TM);                      // (4, 1250)
    joiner_fused<<<grid, 256, DSMEM>>>(enc, dec, W, bias, out);
}

// round 14
// speedup vs baseline: 2.9373x; 2.9373x over previous
#include <cuda_runtime.h>
#include <cuda_fp16.h>
#include <cstdint>

// Problem constants: N=8, T=200, U=100, D=512, V=500
#define JN 8
#define JT 200
#define JU 100
#define JD 512
#define JV 500
#define JM (JN * JT * JU)   // 160000

// GEMM tiling: CTA 128(M) x 128(N), BK=64 fp16 (128B rows, SW128), 3-stage ring
#define TM 128
#define TN 128
#define BKT 64
#define NTILE (JD / BKT)          // 8
#define NBUF 3
#define ASZ (TM * BKT * 2)        // 16384 B
#define BSZ (TN * BKT * 2)        // 16384 B
#define STAGE (ASZ + BSZ)         // 32768 B
#define DSMEM (NBUF * STAGE)      // 98304 B

// Scratch: A = fp16 tanh(enc+dec); Wh = fp16 W padded to 512 rows (500..511 = 0)
__device__ __half g_A[(size_t)JM * JD];
__device__ __half g_Wh[512 * 512];

// ---------------------------------------------------------------------------
__device__ __forceinline__ float mufu_tanh(float x) {
    float y;
    asm("tanh.approx.f32 %0, %1;" : "=f"(y) : "f"(x));
    return y;
}
__device__ __forceinline__ void cpa16(uint32_t dst, const void* src) {
    asm volatile("cp.async.cg.shared.global [%0], [%1], 16;\n" :: "r"(dst), "l"(src));
}

// ================= Producer: tanh -> g_A  and  W -> g_Wh ===================
#define TANH_BLOCKS ((JM * (JD / 8)) / 256)     // 40000
#define W_BLOCKS    ((512 * 64) / 256)          // 128
__global__ __launch_bounds__(256)
void producer(const float* __restrict__ enc, const float* __restrict__ dec,
              const float* __restrict__ W) {
    const int bx = blockIdx.x;
    if (bx < TANH_BLOCKS) {
        int idx = bx * 256 + threadIdx.x;       // one 16B chunk = 8 fp16 of A
        int k8 = idx & 63;                      // JD/8 = 64
        int m  = idx >> 6;
        int n = m / (JT * JU);
        int r = m % (JT * JU);
        int t = r / JU;
        int u = r % JU;
        const float4* ep = (const float4*)(enc + (size_t)(n * JT + t) * JD + k8 * 8);
        const float4* dp = (const float4*)(dec + (size_t)(n * JU + u) * JD + k8 * 8);
        const float4 e0 = ep[0], e1 = ep[1];
        const float4 d0 = dp[0], d1 = dp[1];
        __half2 h[4];
        h[0] = __floats2half2_rn(mufu_tanh(e0.x + d0.x), mufu_tanh(e0.y + d0.y));
        h[1] = __floats2half2_rn(mufu_tanh(e0.z + d0.z), mufu_tanh(e0.w + d0.w));
        h[2] = __floats2half2_rn(mufu_tanh(e1.x + d1.x), mufu_tanh(e1.y + d1.y));
        h[3] = __floats2half2_rn(mufu_tanh(e1.z + d1.z), mufu_tanh(e1.w + d1.w));
        *(uint4*)(g_A + (size_t)m * JD + k8 * 8) = *(const uint4*)h;
    } else {
        int idx = (bx - TANH_BLOCKS) * 256 + threadIdx.x;  // one 16B chunk of Wh
        int row = idx >> 6;
        int c8  = (idx & 63) * 8;
        __half2 h[4] = {__half2{}, __half2{}, __half2{}, __half2{}};
        if (row < JV) {
            const float4* wp = (const float4*)(W + (size_t)row * JD + c8);
            const float4 w0 = wp[0], w1 = wp[1];
            h[0] = __floats2half2_rn(w0.x, w0.y);
            h[1] = __floats2half2_rn(w0.z, w0.w);
            h[2] = __floats2half2_rn(w1.x, w1.y);
            h[3] = __floats2half2_rn(w1.z, w1.w);
        }
        *(uint4*)(g_Wh + (size_t)row * JD + c8) = *(const uint4*)h;
    }
}

// ============================ fp16 GEMM (proven R9) ========================
// out[M,V] = g_A[M,K] @ g_Wh[V,K]^T + bias. 8 warps: 2(M) x 4(N), warp 64x32.
// mma.m16n8k16.f16 fp32-acc; ldmatrix fragment feed, SW128; 3-stage cp.async.
__global__ __launch_bounds__(256, 2)
void joiner_gemm(const float* __restrict__ bias, float* __restrict__ out) {
    extern __shared__ char dsm[];
    const uint32_t smem0 = (uint32_t)__cvta_generic_to_shared(dsm);

    const int tid  = threadIdx.x;
    const int lane = tid & 31;
    const int wid  = tid >> 5;
    const int g    = lane >> 2;     // 0..7
    const int tg   = lane & 3;      // 0..3
    const int wm   = wid & 1;       // warp M row (64 each)
    const int wn   = wid >> 1;      // warp N col (32 each)

    const int m0 = blockIdx.y * TM;
    const int v0 = blockIdx.x * TN;

    // ---- cp.async roles: 8 threads per row (8x16B = full 128B row) --------
    const int kg   = tid & 7;               // 16B segment within row (8 fp16)
    const int rrow = tid >> 3;              // 0..31, rows rrow + 32*j
    const __half* gAp = g_A  + (size_t)(m0 + rrow) * JD + kg * 8;
    const __half* gBp = g_Wh + (size_t)(v0 + rrow) * JD + kg * 8;
    uint32_t dOff[4];
    #pragma unroll
    for (int j = 0; j < 4; j++) {
        const int rw = rrow + 32 * j;
        dOff[j] = (uint32_t)(rw * 128) + 16u * (uint32_t)(kg ^ (rw & 7));
    }

    // ---- ldmatrix per-lane geometry ----------------------------------------
    const int lr = (lane & 7) + 8 * ((lane >> 3) & 1);  // row within 16-row frag
    const int kh = lane >> 4;                           // k-half (0/1)
    uint32_t aOff[4], bOff[2];
    int aXk[4], bXk[2];
    #pragma unroll
    for (int mt = 0; mt < 4; mt++) {
        const int row = wm * 64 + mt * 16 + lr;
        aOff[mt] = (uint32_t)(row * 128);
        aXk[mt]  = row & 7;
    }
    #pragma unroll
    for (int pr = 0; pr < 2; pr++) {
        const int row = wn * 32 + pr * 16 + lr;
        bOff[pr] = (uint32_t)(row * 128);
        bXk[pr]  = row & 7;
    }

    float acc[4][4][4];
    #pragma unroll
    for (int mt = 0; mt < 4; mt++)
        #pragma unroll
        for (int nt = 0; nt < 4; nt++)
            #pragma unroll
            for (int i = 0; i < 4; i++) acc[mt][nt][i] = 0.0f;

    // ---- tile copy: tile p -> slot p%NBUF ----------------------------------
    auto issue_copy = [&](int p) {
        const uint32_t ab = smem0 + (uint32_t)((p % NBUF) * STAGE);
        const uint32_t bb = ab + ASZ;
        const int ko = p * BKT;
        #pragma unroll
        for (int j = 0; j < 4; j++) {
            cpa16(ab + dOff[j], gAp + (size_t)(32 * j) * JD + ko);
            cpa16(bb + dOff[j], gBp + (size_t)(32 * j) * JD + ko);
        }
        asm volatile("cp.async.commit_group;");
    };

    // ---- fragment load for one k16 slice (= 32B = 2 segs) ------------------
    auto load_frags = [&](uint32_t ab, uint32_t bb, int ks,
                          unsigned (*a)[4], unsigned (*b)[2]) {
        const int ksk = (ks << 1) | kh;
        #pragma unroll
        for (int mt = 0; mt < 4; mt++) {
            const uint32_t ad = ab + aOff[mt] + 16u * (uint32_t)(ksk ^ aXk[mt]);
            asm volatile("ldmatrix.sync.aligned.m8n8.x4.shared.b16 {%0,%1,%2,%3}, [%4];"
                         : "=r"(a[mt][0]), "=r"(a[mt][1]), "=r"(a[mt][2]), "=r"(a[mt][3])
                         : "r"(ad));
        }
        #pragma unroll
        for (int pr = 0; pr < 2; pr++) {
            const uint32_t bd = bb + bOff[pr] + 16u * (uint32_t)(ksk ^ bXk[pr]);
            unsigned r0, r1, r2, r3;
            asm volatile("ldmatrix.sync.aligned.m8n8.x4.shared.b16 {%0,%1,%2,%3}, [%4];"
                         : "=r"(r0), "=r"(r1), "=r"(r2), "=r"(r3) : "r"(bd));
            b[pr * 2 + 0][0] = r0;  b[pr * 2 + 1][0] = r1;
            b[pr * 2 + 0][1] = r2;  b[pr * 2 + 1][1] = r3;
        }
    };

    unsigned aF[2][4][4], bF[2][4][2];

    // prologue
    #pragma unroll
    for (int p = 0; p < NBUF - 1; p++) issue_copy(p);

    #pragma unroll 1
    for (int it = 0; it < NTILE; ++it) {
        asm volatile("cp.async.wait_group %0;" :: "n"(NBUF - 2));
        __syncthreads();
        if (it + NBUF - 1 < NTILE) issue_copy(it + NBUF - 1);

        const uint32_t ab = smem0 + (uint32_t)((it % NBUF) * STAGE);
        const uint32_t bb = ab + ASZ;

        load_frags(ab, bb, 0, aF[0], bF[0]);     // preload slice 0

        #pragma unroll
        for (int ks = 0; ks < BKT / 16; ks++) {  // 4 k16 slices
            const int cur = ks & 1;
            if (ks < BKT / 16 - 1)
                load_frags(ab, bb, ks + 1, aF[cur ^ 1], bF[cur ^ 1]);
            #pragma unroll
            for (int mt = 0; mt < 4; mt++)
                #pragma unroll
                for (int nt = 0; nt < 4; nt++) {
                    asm volatile(
                        "mma.sync.aligned.m16n8k16.row.col.f32.f16.f16.f32 "
                        "{%0,%1,%2,%3}, {%4,%5,%6,%7}, {%8,%9}, {%0,%1,%2,%3};"
                        : "+f"(acc[mt][nt][0]), "+f"(acc[mt][nt][1]),
                          "+f"(acc[mt][nt][2]), "+f"(acc[mt][nt][3])
                        : "r"(aF[cur][mt][0]), "r"(aF[cur][mt][1]),
                          "r"(aF[cur][mt][2]), "r"(aF[cur][mt][3]),
                          "r"(bF[cur][nt][0]), "r"(bF[cur][nt][1]));
                }
        }
    }

    // ---- epilogue: bias + float2 stores ------------------------------------
    #pragma unroll
    for (int mt = 0; mt < 4; mt++) {
        const int r0 = m0 + wm * 64 + mt * 16 + g;
        const int r1 = r0 + 8;
        #pragma unroll
        for (int nt = 0; nt < 4; nt++) {
            const int c = v0 + wn * 32 + nt * 8 + tg * 2;
            if (c < JV) {
                const float2 bb2 = *(const float2*)(bias + c);
                float2 o0, o1;
                o0.x = acc[mt][nt][0] + bb2.x;
                o0.y = acc[mt][nt][1] + bb2.y;
                o1.x = acc[mt][nt][2] + bb2.x;
                o1.y = acc[mt][nt][3] + bb2.y;
                *(float2*)(out + (size_t)r0 * JV + c) = o0;
                *(float2*)(out + (size_t)r1 * JV + c) = o1;
            }
        }
    }
}

// ===========================================================================
extern "C" void kernel_launch(void* const* d_in, const int* in_sizes, int n_in,
                              void* d_out, int out_size)
{
    const float* enc  = (const float*)d_in[0];  // (8, 200, 512)
    const float* dec  = (const float*)d_in[1];  // (8, 100, 512)
    const float* W    = (const float*)d_in[2];  // (500, 512)
    const float* bias = (const float*)d_in[3];  // (500,)
    float* out = (float*)d_out;                 // (8, 200, 100, 500)

    producer<<<TANH_BLOCKS + W_BLOCKS, 256>>>(enc, dec, W);

    cudaFuncSetAttribute(joiner_gemm, cudaFuncAttributeMaxDynamicSharedMemorySize, DSMEM);
    dim3 grid(4, JM / TM);                      // (4, 1250)
    joiner_gemm<<<grid, 256, DSMEM>>>(bias, out);
}